// round 14
// baseline (speedup 1.0000x reference)
#include <cuda_runtime.h>
#include <cuda_bf16.h>
#include <math.h>
#include <stdint.h>

#define BATCH 32
#define NNETS 264
#define DIM   375
#define PAIRS 34716
#define PPAD  34928      // 37 * 944, even
#define PSPL  37         // p-splits for big GEMM
#define KSPLIT 944       // rows per p-split = 59 chunks of 16
#define CCHUNK 16        // k-rows per smem chunk (1 mma k16-step)
#define NCH   59
#define NBC   512        // n-cols per block (2KB-wide W row slices)
#define WS_LD 516        // fp32 W smem row stride (512+4) -> banks 8tg+gid
#define PK_W  40         // S smem kpair row stride in u32 (32+8) -> banks 8tg+gid
#define STAGE_F (CCHUNK*WS_LD + 8*PK_W)    // 8256 + 320 = 8576 floats
#define KC_SMEM_BYTES (3*STAGE_F*4)        // 102912 B -> 2 blocks/SM
#define PSPL_E 16        // p-splits for kE
#define RRS   (11.0f/48.0f)

// -------- device scratch (no allocations allowed) --------
__device__ float    g_A  [BATCH*NNETS*32];    // feats @ sm_w1[0:32]  (+ sm_b1 folded in)
__device__ float    g_Bv [BATCH*NNETS*32];    // feats @ sm_w1[32:64]
__device__ uint16_t g_St2[PPAD*32];           // scores bf16, layout [(p>>1)][b][p&1], pad zero
__device__ float    g_C1p[PSPL*BATCH*4096];   // partial c1
__device__ float    g_C1 [BATCH*4096];        // rrelu(c1)
__device__ float    g_c2p[PSPL_E*BATCH*256];  // partial c2

// =====================================================================
// Kernel Z: zero pad kpair rows of g_St2 (also shifts ncu capture to kC)
// =====================================================================
__global__ void __launch_bounds__(256) kZ()
{
    uint32_t* z = reinterpret_cast<uint32_t*>(g_St2) + (PAIRS/2)*32;
    const int nwords = ((PPAD - PAIRS)/2)*32;   // 3392
    for (int u = threadIdx.x + blockIdx.x*256; u < nwords; u += 256)
        z[u] = 0u;
}

// =====================================================================
// Kernel A: feature extractor + similarity layer-1 factorization
// =====================================================================
__global__ void __launch_bounds__(128) kA(
    const float* __restrict__ x,
    const float* __restrict__ w1, const float* __restrict__ b1,
    const float* __restrict__ w2, const float* __restrict__ b2,
    const float* __restrict__ w3, const float* __restrict__ b3,
    const float* __restrict__ sw1, const float* __restrict__ sb1)
{
    __shared__ float sx [16][376];
    __shared__ float sh1[16][68];
    __shared__ float sh2[16][68];
    __shared__ float sf [16][36];
    const int t = threadIdx.x;
    const int row0 = blockIdx.x * 16;

    for (int idx = t; idx < 16*DIM; idx += 128) {
        int r = idx / DIM;
        int d = idx - r*DIM;
        sx[r][d] = x[(size_t)(row0 + r)*DIM + d];
    }
    __syncthreads();

    const int r  = t >> 3;
    const int cg = t & 7;

    // ---- layer 1: 375 -> 64, rrelu ----
    {
        const int c0 = cg * 8;
        float acc[8];
        #pragma unroll
        for (int u = 0; u < 8; u++) acc[u] = 0.f;
        int d = 0;
        for (; d < 372; d += 4) {
            float4 xv = *reinterpret_cast<const float4*>(&sx[r][d]);
            float xa[4] = {xv.x, xv.y, xv.z, xv.w};
            #pragma unroll
            for (int dd = 0; dd < 4; dd++) {
                float xs1 = xa[dd];
                float4 wa = *reinterpret_cast<const float4*>(&w1[(size_t)(d+dd)*64 + c0]);
                float4 wb = *reinterpret_cast<const float4*>(&w1[(size_t)(d+dd)*64 + c0 + 4]);
                acc[0] += xs1*wa.x; acc[1] += xs1*wa.y; acc[2] += xs1*wa.z; acc[3] += xs1*wa.w;
                acc[4] += xs1*wb.x; acc[5] += xs1*wb.y; acc[6] += xs1*wb.z; acc[7] += xs1*wb.w;
            }
        }
        for (; d < DIM; d++) {
            float xs1 = sx[r][d];
            #pragma unroll
            for (int u = 0; u < 8; u++) acc[u] += xs1 * w1[(size_t)d*64 + c0 + u];
        }
        #pragma unroll
        for (int u = 0; u < 8; u++) {
            float v = acc[u] + b1[c0 + u];
            sh1[r][c0 + u] = (v >= 0.f) ? v : v * RRS;
        }
    }
    __syncthreads();

    // ---- layer 2: 64 -> 64, relu ----
    {
        const int c0 = cg * 8;
        float acc[8];
        #pragma unroll
        for (int u = 0; u < 8; u++) acc[u] = 0.f;
        for (int k = 0; k < 64; k += 4) {
            float4 hv = *reinterpret_cast<const float4*>(&sh1[r][k]);
            float ha[4] = {hv.x, hv.y, hv.z, hv.w};
            #pragma unroll
            for (int dd = 0; dd < 4; dd++) {
                float xs1 = ha[dd];
                float4 wa = *reinterpret_cast<const float4*>(&w2[(size_t)(k+dd)*64 + c0]);
                float4 wb = *reinterpret_cast<const float4*>(&w2[(size_t)(k+dd)*64 + c0 + 4]);
                acc[0] += xs1*wa.x; acc[1] += xs1*wa.y; acc[2] += xs1*wa.z; acc[3] += xs1*wa.w;
                acc[4] += xs1*wb.x; acc[5] += xs1*wb.y; acc[6] += xs1*wb.z; acc[7] += xs1*wb.w;
            }
        }
        #pragma unroll
        for (int u = 0; u < 8; u++)
            sh2[r][c0 + u] = fmaxf(acc[u] + b2[c0 + u], 0.f);
    }
    __syncthreads();

    // ---- layer 3: 64 -> 32 (no act) ----
    {
        const int c0 = cg * 4;
        float acc[4] = {0.f, 0.f, 0.f, 0.f};
        for (int k = 0; k < 64; k += 4) {
            float4 hv = *reinterpret_cast<const float4*>(&sh2[r][k]);
            float ha[4] = {hv.x, hv.y, hv.z, hv.w};
            #pragma unroll
            for (int dd = 0; dd < 4; dd++) {
                float xs1 = ha[dd];
                float4 wa = *reinterpret_cast<const float4*>(&w3[(size_t)(k+dd)*32 + c0]);
                acc[0] += xs1*wa.x; acc[1] += xs1*wa.y; acc[2] += xs1*wa.z; acc[3] += xs1*wa.w;
            }
        }
        #pragma unroll
        for (int u = 0; u < 4; u++) sf[r][c0 + u] = acc[u] + b3[c0 + u];
    }
    __syncthreads();

    // ---- similarity layer-1 factorization ----
    {
        const int c0 = cg * 4;
        float aa[4] = {0.f,0.f,0.f,0.f};
        float bb[4] = {0.f,0.f,0.f,0.f};
        for (int k = 0; k < 32; k += 4) {
            float4 fv = *reinterpret_cast<const float4*>(&sf[r][k]);
            float fa[4] = {fv.x, fv.y, fv.z, fv.w};
            #pragma unroll
            for (int dd = 0; dd < 4; dd++) {
                float xs1 = fa[dd];
                float4 wa = *reinterpret_cast<const float4*>(&sw1[(size_t)(k+dd)*32 + c0]);
                float4 wb = *reinterpret_cast<const float4*>(&sw1[(size_t)(k+dd+32)*32 + c0]);
                aa[0] += xs1*wa.x; aa[1] += xs1*wa.y; aa[2] += xs1*wa.z; aa[3] += xs1*wa.w;
                bb[0] += xs1*wb.x; bb[1] += xs1*wb.y; bb[2] += xs1*wb.z; bb[3] += xs1*wb.w;
            }
        }
        size_t base = (size_t)(row0 + r)*32 + c0;
        #pragma unroll
        for (int u = 0; u < 4; u++) {
            g_A [base + u] = aa[u] + sb1[c0 + u];
            g_Bv[base + u] = bb[u];
        }
    }
}

// =====================================================================
// Kernel B: similarity MLP over all (b, i<j) pairs. Triangle tiling 32x32.
// Writes scores bf16 packed: g_St2[(p>>1)*64 + b*2 + (p&1)].
// =====================================================================
__global__ void __launch_bounds__(256) kB(
    const float* __restrict__ smw2, const float* __restrict__ smb2,
    const float* __restrict__ smw3, const float* __restrict__ smb3,
    const float* __restrict__ smw4, const float* __restrict__ smb4)
{
    __shared__ float  bs[32][33];
    __shared__ float4 w2s[32][4];
    __shared__ float4 w3s[16][2];
    __shared__ float  w4s[8];
    __shared__ float  b2s[16];
    __shared__ float  b3s[8];
    __shared__ float  b4s;

    const int t = threadIdx.x;
    const int b = blockIdx.y;

    // decode triangle tile
    int ti = 0, rem = blockIdx.x;
    while (rem >= 9 - ti) { rem -= 9 - ti; ti++; }
    int tj = ti + rem;
    const int i0 = ti*32, j0 = tj*32;

    // stage weights
    for (int u = t; u < 512; u += 256) reinterpret_cast<float*>(w2s)[u] = smw2[u];
    for (int u = t; u < 128; u += 256) reinterpret_cast<float*>(w3s)[u] = smw3[u];
    if (t < 8)  w4s[t] = smw4[t];
    if (t < 16) b2s[t] = smb2[t];
    if (t >= 16 && t < 24) b3s[t-16] = smb3[t-16];
    if (t == 24) b4s = smb4[0];

    // stage b-vectors for the j tile
    for (int u = t; u < 32*32; u += 256) {
        int jl = u >> 5, c = u & 31;
        int j = j0 + jl;
        bs[jl][c] = (j < NNETS) ? g_Bv[((size_t)b*NNETS + j)*32 + c] : 0.f;
    }
    __syncthreads();

    const int il = t & 31;
    const int jg = t >> 5;
    const int i  = i0 + il;
    const bool ivalid = (i < NNETS);

    float a[32];
    if (ivalid) {
        #pragma unroll
        for (int u = 0; u < 8; u++) {
            float4 v = *reinterpret_cast<const float4*>(&g_A[((size_t)b*NNETS + i)*32 + u*4]);
            a[u*4+0]=v.x; a[u*4+1]=v.y; a[u*4+2]=v.z; a[u*4+3]=v.w;
        }
    }

    for (int q = 0; q < 4; q++) {
        int jl = jg + 8*q;
        int j  = j0 + jl;
        if (!ivalid || j >= NNETS || i >= j) continue;

        float h2[16];
        #pragma unroll
        for (int o = 0; o < 16; o++) h2[o] = b2s[o];
        #pragma unroll
        for (int k = 0; k < 32; k++) {
            float v = fmaxf(a[k] + bs[jl][k], 0.f);
            #pragma unroll
            for (int q4 = 0; q4 < 4; q4++) {
                float4 wv = w2s[k][q4];
                h2[q4*4+0] += v*wv.x; h2[q4*4+1] += v*wv.y;
                h2[q4*4+2] += v*wv.z; h2[q4*4+3] += v*wv.w;
            }
        }
        float h3[8];
        #pragma unroll
        for (int o = 0; o < 8; o++) h3[o] = b3s[o];
        #pragma unroll
        for (int k = 0; k < 16; k++) {
            float v = fmaxf(h2[k], 0.f);
            #pragma unroll
            for (int q4 = 0; q4 < 2; q4++) {
                float4 wv = w3s[k][q4];
                h3[q4*4+0] += v*wv.x; h3[q4*4+1] += v*wv.y;
                h3[q4*4+2] += v*wv.z; h3[q4*4+3] += v*wv.w;
            }
        }
        float sv = b4s;
        #pragma unroll
        for (int k = 0; k < 8; k++) sv += fmaxf(h3[k], 0.f) * w4s[k];
        float s = tanhf(sv);

        int p = ((i * (2*NNETS - i - 1)) >> 1) + (j - i - 1);
        __nv_bfloat16 sb16 = __float2bfloat16(s);
        reinterpret_cast<__nv_bfloat16*>(g_St2)[((size_t)(p >> 1))*64 + b*2 + (p & 1)] = sb16;
    }
}

// =====================================================================
// Kernel C: c1 partials = S[32,PPAD] @ cl_w1[PAIRS,4096], bf16 mma.
// 8 n-blocks x 512 cols (2KB-wide W row slices for DRAM row-buffer
// efficiency). 256 thr (8 warps x 64 cols). 3-stage cp.async pipeline.
// grid (8, 37) = 296 blocks = exactly 2/SM.
// =====================================================================
__device__ __forceinline__ void mma_bf16(float c[4], const uint32_t a[4], const uint32_t bb[2])
{
    asm volatile(
        "mma.sync.aligned.m16n8k16.row.col.f32.bf16.bf16.f32 "
        "{%0,%1,%2,%3}, {%4,%5,%6,%7}, {%8,%9}, {%0,%1,%2,%3};\n"
        : "+f"(c[0]), "+f"(c[1]), "+f"(c[2]), "+f"(c[3])
        : "r"(a[0]), "r"(a[1]), "r"(a[2]), "r"(a[3]), "r"(bb[0]), "r"(bb[1]));
}

__device__ __forceinline__ uint32_t cvt_pack(float lo, float hi)
{
    uint32_t r;
    asm("cvt.rn.bf16x2.f32 %0, %1, %2;" : "=r"(r) : "f"(hi), "f"(lo));
    return r;
}

__device__ __forceinline__ void cpasync16(void* dst, const void* src)
{
    uint32_t d = (uint32_t)__cvta_generic_to_shared(dst);
    asm volatile("cp.async.cg.shared.global.L2::256B [%0], [%1], 16;\n" :: "r"(d), "l"(src));
}

__global__ void __launch_bounds__(256) kC(const float* __restrict__ W)
{
    extern __shared__ float sm[];

    const int t    = threadIdx.x;
    const int warp = t >> 5, lane = t & 31;
    const int gid  = lane >> 2, tg = lane & 3;
    const int nb   = blockIdx.x;           // 0..7
    const int ps   = blockIdx.y;           // 0..36
    const int ncol0 = nb * NBC;
    const int wc0   = warp * 64;
    const int pbase = ps * KSPLIT;

    float c[2][8][4];
    #pragma unroll
    for (int m = 0; m < 2; m++)
        #pragma unroll
        for (int n = 0; n < 8; n++)
            #pragma unroll
            for (int u = 0; u < 4; u++) c[m][n][u] = 0.f;

    auto load = [&](int buf, int ch) {
        float* stage = sm + buf*STAGE_F;
        const int prow0 = pbase + ch*CCHUNK;
        // W: 16 rows x 512 floats = 2048 f4; 8 per thread, warp = 512B run
        #pragma unroll
        for (int it = 0; it < 8; it++) {
            int idx = t + it*256;
            int r = idx >> 7, c4 = (idx & 127) * 4;
            int pr = prow0 + r; if (pr > PAIRS-1) pr = PAIRS-1;
            cpasync16(stage + r*WS_LD + c4, W + (size_t)pr*4096 + ncol0 + c4);
        }
        // S: 8 kpair rows x 128 B; threads 0..63
        if (t < 64) {
            int r = t >> 3, c16 = (t & 7) * 16;
            const char* src = reinterpret_cast<const char*>(g_St2)
                            + ((size_t)(prow0 >> 1) + r) * 128 + c16;
            char* dst = reinterpret_cast<char*>(stage + CCHUNK*WS_LD) + r*(PK_W*4) + c16;
            cpasync16(dst, src);
        }
    };

    load(0, 0);
    asm volatile("cp.async.commit_group;\n");
    load(1, 1);
    asm volatile("cp.async.commit_group;\n");

    for (int ch = 0; ch < NCH; ch++) {
        if (ch + 1 < NCH) {
            asm volatile("cp.async.wait_group 1;\n");
        } else {
            asm volatile("cp.async.wait_group 0;\n");
        }
        __syncthreads();

        if (ch + 2 < NCH) {
            load((ch+2) % 3, ch+2);
            asm volatile("cp.async.commit_group;\n");
        }

        const float*    wb = sm + (ch % 3)*STAGE_F;
        const uint32_t* sb = reinterpret_cast<const uint32_t*>(wb + CCHUNK*WS_LD);

        // A fragments (one k16 step)
        const uint32_t* Sr  = sb + tg*PK_W;
        const uint32_t* Sr4 = Sr + 4*PK_W;
        uint32_t a0[4] = { Sr[gid],    Sr[gid+8],  Sr4[gid],    Sr4[gid+8]  };
        uint32_t a1[4] = { Sr[gid+16], Sr[gid+24], Sr4[gid+16], Sr4[gid+24] };

        // B fragments: fp32 smem -> bf16x2, 8 n-tiles
        const float* Wr = wb + (2*tg)*WS_LD + wc0 + gid;
        #pragma unroll
        for (int nt = 0; nt < 8; nt++) {
            const float* Wn = Wr + nt*8;
            uint32_t bfr[2];
            bfr[0] = cvt_pack(Wn[0],       Wn[WS_LD]);
            bfr[1] = cvt_pack(Wn[8*WS_LD], Wn[9*WS_LD]);
            mma_bf16(c[0][nt], a0, bfr);
            mma_bf16(c[1][nt], a1, bfr);
        }
        __syncthreads();
    }

    #pragma unroll
    for (int mt = 0; mt < 2; mt++)
        #pragma unroll
        for (int nt = 0; nt < 8; nt++) {
            int gcol = ncol0 + wc0 + nt*8 + tg*2;
            int row  = mt*16 + gid;
            float* o = g_C1p + ((size_t)ps*32 + row)*4096 + gcol;
            *reinterpret_cast<float2*>(o)                  = make_float2(c[mt][nt][0], c[mt][nt][1]);
            *reinterpret_cast<float2*>(o + (size_t)8*4096) = make_float2(c[mt][nt][2], c[mt][nt][3]);
        }
}

// =====================================================================
// Kernel D: reduce c1 partials + bias + rrelu -> g_C1
// =====================================================================
__global__ void __launch_bounds__(256) kD(const float* __restrict__ clb1)
{
    int idx = blockIdx.x*256 + threadIdx.x;   // < 131072
    float acc = 0.f;
    #pragma unroll
    for (int ps = 0; ps < PSPL; ps++) acc += g_C1p[(size_t)ps*131072 + idx];
    float v = acc + clb1[idx & 4095];
    g_C1[idx] = (v >= 0.f) ? v : v * RRS;
}

// =====================================================================
// Kernel E: c2 partials = g_C1[32,4096] @ cl_w2[4096,256]
// =====================================================================
__global__ void __launch_bounds__(256) kE(const float* __restrict__ w2)
{
    const int kg = blockIdx.x & 15;
    const int ps = blockIdx.x >> 4;
    const int t  = threadIdx.x;
    const int kcol = kg*16 + (t & 15);
    const int tb = t >> 4;
    const int b0 = tb*2, b1 = b0 + 1;
    float acc0 = 0.f, acc1 = 0.f;
    const float* c1a = g_C1 + (size_t)b0*4096;
    const float* c1b = g_C1 + (size_t)b1*4096;
    const int pstart = ps*256;
    #pragma unroll 8
    for (int p = pstart; p < pstart + 256; p++) {
        float w = w2[(size_t)p*256 + kcol];
        acc0 += c1a[p]*w;
        acc1 += c1b[p]*w;
    }
    g_c2p[((size_t)ps*32 + b0)*256 + kcol] = acc0;
    g_c2p[((size_t)ps*32 + b1)*256 + kcol] = acc1;
}

// =====================================================================
// Kernel F: reduce c2 + relu, c3, c4, log_softmax. Single block.
// =====================================================================
__global__ void __launch_bounds__(256) kF(
    const float* __restrict__ clb2,
    const float* __restrict__ w3, const float* __restrict__ clb3,
    const float* __restrict__ w4, const float* __restrict__ clb4,
    float* __restrict__ out)
{
    __shared__ float c2s[32][256];
    __shared__ float c3s[32][65];
    const int t = threadIdx.x;

    for (int idx = t; idx < 8192; idx += 256) {
        float acc = 0.f;
        #pragma unroll
        for (int ps = 0; ps < PSPL_E; ps++) acc += g_c2p[(size_t)ps*8192 + idx];
        acc += clb2[idx & 255];
        c2s[idx >> 8][idx & 255] = fmaxf(acc, 0.f);
    }
    __syncthreads();

    for (int o = t; o < 2048; o += 256) {
        int b = o >> 6, k = o & 63;
        float acc = clb3[k];
        for (int p = 0; p < 256; p++) acc += c2s[b][p] * w3[(size_t)p*64 + k];
        c3s[b][k] = fmaxf(acc, 0.f);
    }
    __syncthreads();

    if (t < 32) {
        const int b = t;
        float l[3];
        #pragma unroll
        for (int j = 0; j < 3; j++) {
            float acc = clb4[j];
            for (int k = 0; k < 64; k++) acc += c3s[b][k] * w4[k*3 + j];
            l[j] = acc;
        }
        float m = fmaxf(l[0], fmaxf(l[1], l[2]));
        float se = expf(l[0]-m) + expf(l[1]-m) + expf(l[2]-m);
        float ls = m + logf(se);
        out[b*3+0] = l[0] - ls;
        out[b*3+1] = l[1] - ls;
        out[b*3+2] = l[2] - ls;
    }
}

// =====================================================================
extern "C" void kernel_launch(void* const* d_in, const int* in_sizes, int n_in,
                              void* d_out, int out_size)
{
    const float* x    = (const float*)d_in[0];
    const float* few1 = (const float*)d_in[1];
    const float* feb1 = (const float*)d_in[2];
    const float* few2 = (const float*)d_in[3];
    const float* feb2 = (const float*)d_in[4];
    const float* few3 = (const float*)d_in[5];
    const float* feb3 = (const float*)d_in[6];
    const float* smw1 = (const float*)d_in[7];
    const float* smb1 = (const float*)d_in[8];
    const float* smw2 = (const float*)d_in[9];
    const float* smb2 = (const float*)d_in[10];
    const float* smw3 = (const float*)d_in[11];
    const float* smb3 = (const float*)d_in[12];
    const float* smw4 = (const float*)d_in[13];
    const float* smb4 = (const float*)d_in[14];
    const float* clw1 = (const float*)d_in[15];
    const float* clb1 = (const float*)d_in[16];
    const float* clw2 = (const float*)d_in[17];
    const float* clb2 = (const float*)d_in[18];
    const float* clw3 = (const float*)d_in[19];
    const float* clb3 = (const float*)d_in[20];
    const float* clw4 = (const float*)d_in[21];
    const float* clb4 = (const float*)d_in[22];

    static bool attr_set = false;
    if (!attr_set) {
        cudaFuncSetAttribute(kC, cudaFuncAttributeMaxDynamicSharedMemorySize,
                             KC_SMEM_BYTES);
        attr_set = true;
    }

    kZ<<<14, 256>>>();
    kA<<<528, 128>>>(x, few1, feb1, few2, feb2, few3, feb3, smw1, smb1);
    kB<<<dim3(45, 32), 256>>>(smw2, smb2, smw3, smb3, smw4, smb4);
    kC<<<dim3(8, PSPL), 256, KC_SMEM_BYTES>>>(clw1);
    kD<<<512, 256>>>(clb1);
    kE<<<256, 256>>>(clw2);
    kF<<<1, 256>>>(clb2, clw3, clb3, clw4, clb4, (float*)d_out);
}

// round 15
// speedup vs baseline: 1.0941x; 1.0941x over previous
#include <cuda_runtime.h>
#include <cuda_bf16.h>
#include <math.h>
#include <stdint.h>

#define BATCH 32
#define NNETS 264
#define DIM   375
#define PAIRS 34716
#define PPAD  34928      // 37 * 944, even
#define PSPL  37         // p-splits for big GEMM
#define KSPLIT 944       // rows per p-split = 59 chunks of 16
#define CCHUNK 16        // k-rows per smem chunk (1 mma k16-step)
#define NCH   59
#define NBC   512        // n-cols per block (2KB-wide W row slices)
#define WS_LD 516        // fp32 W smem row stride (512+4) -> banks 8tg+gid
#define PK_W  40         // S smem kpair row stride in u32 (32+8) -> banks 8tg+gid
#define STAGE_F (CCHUNK*WS_LD + 8*PK_W)    // 8256 + 320 = 8576 floats
#define KC_SMEM_BYTES (3*STAGE_F*4)        // 102912 B -> 2 blocks/SM
#define PSPL_E 16        // p-splits for kE
#define RRS   (11.0f/48.0f)

typedef unsigned long long ull;

// -------- device scratch (no allocations allowed) --------
__device__ float    g_A  [BATCH*NNETS*32];    // feats @ sm_w1[0:32]  (+ sm_b1 folded in)
__device__ float    g_Bv [BATCH*NNETS*32];    // feats @ sm_w1[32:64]
__device__ uint16_t g_St2[PPAD*32];           // scores bf16, layout [(p>>1)][b][p&1], pad zero
__device__ float    g_C1p[PSPL*BATCH*4096];   // partial c1
__device__ float    g_C1 [BATCH*4096];        // rrelu(c1)
__device__ float    g_c2p[PSPL_E*BATCH*256];  // partial c2
__device__ float    g_C3 [BATCH*64];          // relu(c3)

// ---- packed fp32x2 helpers (Blackwell FFMA2) ----
__device__ __forceinline__ ull pk2(float lo, float hi)
{
    ull r;
    asm("mov.b64 %0, {%1, %2};" : "=l"(r) : "f"(lo), "f"(hi));
    return r;
}
__device__ __forceinline__ void upk2(float& lo, float& hi, ull v)
{
    asm("mov.b64 {%0, %1}, %2;" : "=f"(lo), "=f"(hi) : "l"(v));
}
__device__ __forceinline__ void fma_x2(ull& d, ull a, ull b)
{
    asm("fma.rn.f32x2 %0, %1, %2, %0;" : "+l"(d) : "l"(a), "l"(b));
}
__device__ __forceinline__ float tanh_fast(float x)
{
    float r;
    asm("tanh.approx.f32 %0, %1;" : "=f"(r) : "f"(x));
    return r;
}

// =====================================================================
// Kernel Z: zero pad kpair rows of g_St2
// =====================================================================
__global__ void __launch_bounds__(256) kZ()
{
    uint32_t* z = reinterpret_cast<uint32_t*>(g_St2) + (PAIRS/2)*32;
    const int nwords = ((PPAD - PAIRS)/2)*32;   // 3392
    for (int u = threadIdx.x + blockIdx.x*256; u < nwords; u += 256*14)
        z[u] = 0u;
}

// Kernel Z2: tiny dummy (shifts ncu capture slot onto kB). Idempotent.
__global__ void kZ2()
{
    uint32_t* z = reinterpret_cast<uint32_t*>(g_St2) + (PAIRS/2)*32;
    if (threadIdx.x < 64) z[threadIdx.x] = 0u;
}

// =====================================================================
// Kernel A: feature extractor + similarity layer-1 factorization
// =====================================================================
__global__ void __launch_bounds__(128) kA(
    const float* __restrict__ x,
    const float* __restrict__ w1, const float* __restrict__ b1,
    const float* __restrict__ w2, const float* __restrict__ b2,
    const float* __restrict__ w3, const float* __restrict__ b3,
    const float* __restrict__ sw1, const float* __restrict__ sb1)
{
    __shared__ float sx [16][376];
    __shared__ float sh1[16][68];
    __shared__ float sh2[16][68];
    __shared__ float sf [16][36];
    const int t = threadIdx.x;
    const int row0 = blockIdx.x * 16;

    for (int idx = t; idx < 16*DIM; idx += 128) {
        int r = idx / DIM;
        int d = idx - r*DIM;
        sx[r][d] = x[(size_t)(row0 + r)*DIM + d];
    }
    __syncthreads();

    const int r  = t >> 3;
    const int cg = t & 7;

    // ---- layer 1: 375 -> 64, rrelu ----
    {
        const int c0 = cg * 8;
        float acc[8];
        #pragma unroll
        for (int u = 0; u < 8; u++) acc[u] = 0.f;
        int d = 0;
        for (; d < 372; d += 4) {
            float4 xv = *reinterpret_cast<const float4*>(&sx[r][d]);
            float xa[4] = {xv.x, xv.y, xv.z, xv.w};
            #pragma unroll
            for (int dd = 0; dd < 4; dd++) {
                float xs1 = xa[dd];
                float4 wa = *reinterpret_cast<const float4*>(&w1[(size_t)(d+dd)*64 + c0]);
                float4 wb = *reinterpret_cast<const float4*>(&w1[(size_t)(d+dd)*64 + c0 + 4]);
                acc[0] += xs1*wa.x; acc[1] += xs1*wa.y; acc[2] += xs1*wa.z; acc[3] += xs1*wa.w;
                acc[4] += xs1*wb.x; acc[5] += xs1*wb.y; acc[6] += xs1*wb.z; acc[7] += xs1*wb.w;
            }
        }
        for (; d < DIM; d++) {
            float xs1 = sx[r][d];
            #pragma unroll
            for (int u = 0; u < 8; u++) acc[u] += xs1 * w1[(size_t)d*64 + c0 + u];
        }
        #pragma unroll
        for (int u = 0; u < 8; u++) {
            float v = acc[u] + b1[c0 + u];
            sh1[r][c0 + u] = (v >= 0.f) ? v : v * RRS;
        }
    }
    __syncthreads();

    // ---- layer 2: 64 -> 64, relu ----
    {
        const int c0 = cg * 8;
        float acc[8];
        #pragma unroll
        for (int u = 0; u < 8; u++) acc[u] = 0.f;
        for (int k = 0; k < 64; k += 4) {
            float4 hv = *reinterpret_cast<const float4*>(&sh1[r][k]);
            float ha[4] = {hv.x, hv.y, hv.z, hv.w};
            #pragma unroll
            for (int dd = 0; dd < 4; dd++) {
                float xs1 = ha[dd];
                float4 wa = *reinterpret_cast<const float4*>(&w2[(size_t)(k+dd)*64 + c0]);
                float4 wb = *reinterpret_cast<const float4*>(&w2[(size_t)(k+dd)*64 + c0 + 4]);
                acc[0] += xs1*wa.x; acc[1] += xs1*wa.y; acc[2] += xs1*wa.z; acc[3] += xs1*wa.w;
                acc[4] += xs1*wb.x; acc[5] += xs1*wb.y; acc[6] += xs1*wb.z; acc[7] += xs1*wb.w;
            }
        }
        #pragma unroll
        for (int u = 0; u < 8; u++)
            sh2[r][c0 + u] = fmaxf(acc[u] + b2[c0 + u], 0.f);
    }
    __syncthreads();

    // ---- layer 3: 64 -> 32 (no act) ----
    {
        const int c0 = cg * 4;
        float acc[4] = {0.f, 0.f, 0.f, 0.f};
        for (int k = 0; k < 64; k += 4) {
            float4 hv = *reinterpret_cast<const float4*>(&sh2[r][k]);
            float ha[4] = {hv.x, hv.y, hv.z, hv.w};
            #pragma unroll
            for (int dd = 0; dd < 4; dd++) {
                float xs1 = ha[dd];
                float4 wa = *reinterpret_cast<const float4*>(&w3[(size_t)(k+dd)*32 + c0]);
                acc[0] += xs1*wa.x; acc[1] += xs1*wa.y; acc[2] += xs1*wa.z; acc[3] += xs1*wa.w;
            }
        }
        #pragma unroll
        for (int u = 0; u < 4; u++) sf[r][c0 + u] = acc[u] + b3[c0 + u];
    }
    __syncthreads();

    // ---- similarity layer-1 factorization ----
    {
        const int c0 = cg * 4;
        float aa[4] = {0.f,0.f,0.f,0.f};
        float bb[4] = {0.f,0.f,0.f,0.f};
        for (int k = 0; k < 32; k += 4) {
            float4 fv = *reinterpret_cast<const float4*>(&sf[r][k]);
            float fa[4] = {fv.x, fv.y, fv.z, fv.w};
            #pragma unroll
            for (int dd = 0; dd < 4; dd++) {
                float xs1 = fa[dd];
                float4 wa = *reinterpret_cast<const float4*>(&sw1[(size_t)(k+dd)*32 + c0]);
                float4 wb = *reinterpret_cast<const float4*>(&sw1[(size_t)(k+dd+32)*32 + c0]);
                aa[0] += xs1*wa.x; aa[1] += xs1*wa.y; aa[2] += xs1*wa.z; aa[3] += xs1*wa.w;
                bb[0] += xs1*wb.x; bb[1] += xs1*wb.y; bb[2] += xs1*wb.z; bb[3] += xs1*wb.w;
            }
        }
        size_t base = (size_t)(row0 + r)*32 + c0;
        #pragma unroll
        for (int u = 0; u < 4; u++) {
            g_A [base + u] = aa[u] + sb1[c0 + u];
            g_Bv[base + u] = bb[u];
        }
    }
}

// =====================================================================
// Kernel B: similarity MLP over all (b, i<j) pairs. Triangle tiling 32x32.
// Packed fp32x2: each thread evaluates 2 j's per packed pass (2 passes).
// Writes scores bf16 packed: g_St2[(p>>1)*64 + b*2 + (p&1)].
// =====================================================================
__global__ void __launch_bounds__(256) kB(
    const float* __restrict__ smw2, const float* __restrict__ smb2,
    const float* __restrict__ smw3, const float* __restrict__ smb3,
    const float* __restrict__ smw4, const float* __restrict__ smb4)
{
    __shared__ float bs[32][33];
    __shared__ __align__(16) ull w2pk[32][16];   // (w,w) duplicated pairs
    __shared__ __align__(16) ull w3pk[16][8];
    __shared__ ull  b2pk[16];
    __shared__ ull  b3pk[8];
    __shared__ float w4s[8];
    __shared__ float b4sv;

    const int t = threadIdx.x;
    const int b = blockIdx.y;

    // decode triangle tile
    int ti = 0, rem = blockIdx.x;
    while (rem >= 9 - ti) { rem -= 9 - ti; ti++; }
    int tj = ti + rem;
    const int i0 = ti*32, j0 = tj*32;

    // stage packed weights
    for (int u = t; u < 512; u += 256) { float w = smw2[u]; w2pk[u>>4][u&15] = pk2(w, w); }
    if (t < 128) { float w = smw3[t]; w3pk[t>>3][t&7] = pk2(w, w); }
    if (t >= 128 && t < 144) { float v = smb2[t-128]; b2pk[t-128] = pk2(v, v); }
    if (t >= 144 && t < 152) { float v = smb3[t-144]; b3pk[t-144] = pk2(v, v); }
    if (t >= 152 && t < 160) w4s[t-152] = smw4[t-152];
    if (t == 160) b4sv = smb4[0];

    // stage b-vectors for the j tile
    for (int u = t; u < 32*32; u += 256) {
        int jl = u >> 5, c = u & 31;
        int j = j0 + jl;
        bs[jl][c] = (j < NNETS) ? g_Bv[((size_t)b*NNETS + j)*32 + c] : 0.f;
    }
    __syncthreads();

    const int il = t & 31;
    const int jg = t >> 5;
    const int i  = i0 + il;
    const bool ivalid = (i < NNETS);

    float a[32];
    #pragma unroll
    for (int u = 0; u < 8; u++) {
        float4 v;
        if (ivalid)
            v = *reinterpret_cast<const float4*>(&g_A[((size_t)b*NNETS + i)*32 + u*4]);
        else
            v = make_float4(0.f, 0.f, 0.f, 0.f);
        a[u*4+0]=v.x; a[u*4+1]=v.y; a[u*4+2]=v.z; a[u*4+3]=v.w;
    }

    #pragma unroll
    for (int qq = 0; qq < 2; qq++) {
        const int jl0 = jg + 16*qq;
        const int jl1 = jl0 + 8;
        const int jA  = j0 + jl0;
        const int jB  = j0 + jl1;
        const bool vA = ivalid && (jA < NNETS) && (i < jA);
        const bool vB = ivalid && (jB < NNETS) && (i < jB);
        if (!__any_sync(0xFFFFFFFFu, vA || vB)) continue;

        ull h2p[16];
        #pragma unroll
        for (int o = 0; o < 16; o++) h2p[o] = b2pk[o];

        #pragma unroll
        for (int k = 0; k < 32; k++) {
            float v0 = fmaxf(a[k] + bs[jl0][k], 0.f);
            float v1 = fmaxf(a[k] + bs[jl1][k], 0.f);
            ull vv = pk2(v0, v1);
            #pragma unroll
            for (int o2 = 0; o2 < 8; o2++) {
                ulonglong2 ww = *reinterpret_cast<const ulonglong2*>(&w2pk[k][o2*2]);
                fma_x2(h2p[o2*2+0], vv, ww.x);
                fma_x2(h2p[o2*2+1], vv, ww.y);
            }
        }

        ull h3p[8];
        #pragma unroll
        for (int o = 0; o < 8; o++) h3p[o] = b3pk[o];
        #pragma unroll
        for (int k = 0; k < 16; k++) {
            float lo, hi; upk2(lo, hi, h2p[k]);
            ull vv = pk2(fmaxf(lo, 0.f), fmaxf(hi, 0.f));
            #pragma unroll
            for (int o2 = 0; o2 < 4; o2++) {
                ulonglong2 ww = *reinterpret_cast<const ulonglong2*>(&w3pk[k][o2*2]);
                fma_x2(h3p[o2*2+0], vv, ww.x);
                fma_x2(h3p[o2*2+1], vv, ww.y);
            }
        }

        float sv0 = b4sv, sv1 = b4sv;
        #pragma unroll
        for (int k = 0; k < 8; k++) {
            float lo, hi; upk2(lo, hi, h3p[k]);
            sv0 += fmaxf(lo, 0.f) * w4s[k];
            sv1 += fmaxf(hi, 0.f) * w4s[k];
        }

        if (vA) {
            float s = tanh_fast(sv0);
            int p = ((i * (2*NNETS - i - 1)) >> 1) + (jA - i - 1);
            reinterpret_cast<__nv_bfloat16*>(g_St2)[((size_t)(p >> 1))*64 + b*2 + (p & 1)]
                = __float2bfloat16(s);
        }
        if (vB) {
            float s = tanh_fast(sv1);
            int p = ((i * (2*NNETS - i - 1)) >> 1) + (jB - i - 1);
            reinterpret_cast<__nv_bfloat16*>(g_St2)[((size_t)(p >> 1))*64 + b*2 + (p & 1)]
                = __float2bfloat16(s);
        }
    }
}

// =====================================================================
// Kernel C: c1 partials = S[32,PPAD] @ cl_w1[PAIRS,4096], bf16 mma.
// 8 n-blocks x 512 cols. 256 thr (8 warps x 64 cols). 3-stage cp.async.
// grid (8, 37) = 296 blocks = exactly 2/SM.
// =====================================================================
__device__ __forceinline__ void mma_bf16(float c[4], const uint32_t a[4], const uint32_t bb[2])
{
    asm volatile(
        "mma.sync.aligned.m16n8k16.row.col.f32.bf16.bf16.f32 "
        "{%0,%1,%2,%3}, {%4,%5,%6,%7}, {%8,%9}, {%0,%1,%2,%3};\n"
        : "+f"(c[0]), "+f"(c[1]), "+f"(c[2]), "+f"(c[3])
        : "r"(a[0]), "r"(a[1]), "r"(a[2]), "r"(a[3]), "r"(bb[0]), "r"(bb[1]));
}

__device__ __forceinline__ uint32_t cvt_pack(float lo, float hi)
{
    uint32_t r;
    asm("cvt.rn.bf16x2.f32 %0, %1, %2;" : "=r"(r) : "f"(hi), "f"(lo));
    return r;
}

__device__ __forceinline__ void cpasync16(void* dst, const void* src)
{
    uint32_t d = (uint32_t)__cvta_generic_to_shared(dst);
    asm volatile("cp.async.cg.shared.global.L2::256B [%0], [%1], 16;\n" :: "r"(d), "l"(src));
}

__global__ void __launch_bounds__(256) kC(const float* __restrict__ W)
{
    extern __shared__ float sm[];

    const int t    = threadIdx.x;
    const int warp = t >> 5, lane = t & 31;
    const int gid  = lane >> 2, tg = lane & 3;
    const int nb   = blockIdx.x;           // 0..7
    const int ps   = blockIdx.y;           // 0..36
    const int ncol0 = nb * NBC;
    const int wc0   = warp * 64;
    const int pbase = ps * KSPLIT;

    float c[2][8][4];
    #pragma unroll
    for (int m = 0; m < 2; m++)
        #pragma unroll
        for (int n = 0; n < 8; n++)
            #pragma unroll
            for (int u = 0; u < 4; u++) c[m][n][u] = 0.f;

    auto load = [&](int buf, int ch) {
        float* stage = sm + buf*STAGE_F;
        const int prow0 = pbase + ch*CCHUNK;
        #pragma unroll
        for (int it = 0; it < 8; it++) {
            int idx = t + it*256;
            int r = idx >> 7, c4 = (idx & 127) * 4;
            int pr = prow0 + r; if (pr > PAIRS-1) pr = PAIRS-1;
            cpasync16(stage + r*WS_LD + c4, W + (size_t)pr*4096 + ncol0 + c4);
        }
        if (t < 64) {
            int r = t >> 3, c16 = (t & 7) * 16;
            const char* src = reinterpret_cast<const char*>(g_St2)
                            + ((size_t)(prow0 >> 1) + r) * 128 + c16;
            char* dst = reinterpret_cast<char*>(stage + CCHUNK*WS_LD) + r*(PK_W*4) + c16;
            cpasync16(dst, src);
        }
    };

    load(0, 0);
    asm volatile("cp.async.commit_group;\n");
    load(1, 1);
    asm volatile("cp.async.commit_group;\n");

    for (int ch = 0; ch < NCH; ch++) {
        if (ch + 1 < NCH) {
            asm volatile("cp.async.wait_group 1;\n");
        } else {
            asm volatile("cp.async.wait_group 0;\n");
        }
        __syncthreads();

        if (ch + 2 < NCH) {
            load((ch+2) % 3, ch+2);
            asm volatile("cp.async.commit_group;\n");
        }

        const float*    wb = sm + (ch % 3)*STAGE_F;
        const uint32_t* sb = reinterpret_cast<const uint32_t*>(wb + CCHUNK*WS_LD);

        const uint32_t* Sr  = sb + tg*PK_W;
        const uint32_t* Sr4 = Sr + 4*PK_W;
        uint32_t a0[4] = { Sr[gid],    Sr[gid+8],  Sr4[gid],    Sr4[gid+8]  };
        uint32_t a1[4] = { Sr[gid+16], Sr[gid+24], Sr4[gid+16], Sr4[gid+24] };

        const float* Wr = wb + (2*tg)*WS_LD + wc0 + gid;
        #pragma unroll
        for (int nt = 0; nt < 8; nt++) {
            const float* Wn = Wr + nt*8;
            uint32_t bfr[2];
            bfr[0] = cvt_pack(Wn[0],       Wn[WS_LD]);
            bfr[1] = cvt_pack(Wn[8*WS_LD], Wn[9*WS_LD]);
            mma_bf16(c[0][nt], a0, bfr);
            mma_bf16(c[1][nt], a1, bfr);
        }
        __syncthreads();
    }

    #pragma unroll
    for (int mt = 0; mt < 2; mt++)
        #pragma unroll
        for (int nt = 0; nt < 8; nt++) {
            int gcol = ncol0 + wc0 + nt*8 + tg*2;
            int row  = mt*16 + gid;
            float* o = g_C1p + ((size_t)ps*32 + row)*4096 + gcol;
            *reinterpret_cast<float2*>(o)                  = make_float2(c[mt][nt][0], c[mt][nt][1]);
            *reinterpret_cast<float2*>(o + (size_t)8*4096) = make_float2(c[mt][nt][2], c[mt][nt][3]);
        }
}

// =====================================================================
// Kernel D: reduce c1 partials + bias + rrelu -> g_C1
// =====================================================================
__global__ void __launch_bounds__(256) kD(const float* __restrict__ clb1)
{
    int idx = blockIdx.x*256 + threadIdx.x;   // < 131072
    float acc = 0.f;
    #pragma unroll
    for (int ps = 0; ps < PSPL; ps++) acc += g_C1p[(size_t)ps*131072 + idx];
    float v = acc + clb1[idx & 4095];
    g_C1[idx] = (v >= 0.f) ? v : v * RRS;
}

// =====================================================================
// Kernel E: c2 partials = g_C1[32,4096] @ cl_w2[4096,256]
// =====================================================================
__global__ void __launch_bounds__(256) kE(const float* __restrict__ w2)
{
    const int kg = blockIdx.x & 15;
    const int ps = blockIdx.x >> 4;
    const int t  = threadIdx.x;
    const int kcol = kg*16 + (t & 15);
    const int tb = t >> 4;
    const int b0 = tb*2, b1 = b0 + 1;
    float acc0 = 0.f, acc1 = 0.f;
    const float* c1a = g_C1 + (size_t)b0*4096;
    const float* c1b = g_C1 + (size_t)b1*4096;
    const int pstart = ps*256;
    #pragma unroll 8
    for (int p = pstart; p < pstart + 256; p++) {
        float w = w2[(size_t)p*256 + kcol];
        acc0 += c1a[p]*w;
        acc1 += c1b[p]*w;
    }
    g_c2p[((size_t)ps*32 + b0)*256 + kcol] = acc0;
    g_c2p[((size_t)ps*32 + b1)*256 + kcol] = acc1;
}

// =====================================================================
// Kernel F1: per-subject c2 reduce + relu + c3 + relu -> g_C3. 32 blocks.
// =====================================================================
__global__ void __launch_bounds__(256) kF1(
    const float* __restrict__ clb2,
    const float* __restrict__ w3, const float* __restrict__ clb3)
{
    __shared__ float c2s[256];
    const int b = blockIdx.x;
    const int t = threadIdx.x;

    float acc = 0.f;
    #pragma unroll
    for (int ps = 0; ps < PSPL_E; ps++) acc += g_c2p[(size_t)ps*8192 + b*256 + t];
    c2s[t] = fmaxf(acc + clb2[t], 0.f);
    __syncthreads();

    if (t < 64) {
        float acc3 = clb3[t];
        #pragma unroll 8
        for (int p = 0; p < 256; p++) acc3 += c2s[p] * w3[(size_t)p*64 + t];
        g_C3[b*64 + t] = fmaxf(acc3, 0.f);
    }
}

// =====================================================================
// Kernel F2: c4 + log_softmax. 1 block x 32 threads (thread = subject).
// =====================================================================
__global__ void __launch_bounds__(32) kF2(
    const float* __restrict__ w4, const float* __restrict__ clb4,
    float* __restrict__ out)
{
    const int b = threadIdx.x;
    float l[3];
    #pragma unroll
    for (int j = 0; j < 3; j++) {
        float acc = clb4[j];
        #pragma unroll 8
        for (int k = 0; k < 64; k++) acc += g_C3[b*64 + k] * w4[k*3 + j];
        l[j] = acc;
    }
    float m = fmaxf(l[0], fmaxf(l[1], l[2]));
    float se = expf(l[0]-m) + expf(l[1]-m) + expf(l[2]-m);
    float ls = m + logf(se);
    out[b*3+0] = l[0] - ls;
    out[b*3+1] = l[1] - ls;
    out[b*3+2] = l[2] - ls;
}

// =====================================================================
extern "C" void kernel_launch(void* const* d_in, const int* in_sizes, int n_in,
                              void* d_out, int out_size)
{
    const float* x    = (const float*)d_in[0];
    const float* few1 = (const float*)d_in[1];
    const float* feb1 = (const float*)d_in[2];
    const float* few2 = (const float*)d_in[3];
    const float* feb2 = (const float*)d_in[4];
    const float* few3 = (const float*)d_in[5];
    const float* feb3 = (const float*)d_in[6];
    const float* smw1 = (const float*)d_in[7];
    const float* smb1 = (const float*)d_in[8];
    const float* smw2 = (const float*)d_in[9];
    const float* smb2 = (const float*)d_in[10];
    const float* smw3 = (const float*)d_in[11];
    const float* smb3 = (const float*)d_in[12];
    const float* smw4 = (const float*)d_in[13];
    const float* smb4 = (const float*)d_in[14];
    const float* clw1 = (const float*)d_in[15];
    const float* clb1 = (const float*)d_in[16];
    const float* clw2 = (const float*)d_in[17];
    const float* clb2 = (const float*)d_in[18];
    const float* clw3 = (const float*)d_in[19];
    const float* clb3 = (const float*)d_in[20];
    const float* clw4 = (const float*)d_in[21];
    const float* clb4 = (const float*)d_in[22];

    static bool attr_set = false;
    if (!attr_set) {
        cudaFuncSetAttribute(kC, cudaFuncAttributeMaxDynamicSharedMemorySize,
                             KC_SMEM_BYTES);
        attr_set = true;
    }

    kZ<<<14, 256>>>();
    kA<<<528, 128>>>(x, few1, feb1, few2, feb2, few3, feb3, smw1, smb1);
    kZ2<<<1, 64>>>();
    kB<<<dim3(45, 32), 256>>>(smw2, smb2, smw3, smb3, smw4, smb4);
    kC<<<dim3(8, PSPL), 256, KC_SMEM_BYTES>>>(clw1);
    kD<<<512, 256>>>(clb1);
    kE<<<256, 256>>>(clw2);
    kF1<<<32, 256>>>(clb2, clw3, clb3);
    kF2<<<1, 32>>>(clw4, clb4, (float*)d_out);
}